// round 9
// baseline (speedup 1.0000x reference)
#include <cuda_runtime.h>

#define EPSV 1e-3f
#define N_0 40000
#define N_1 20000
#define N_2 8000
#define H_0 496
#define W_0 432
#define H_1 248
#define W_1 216
#define H_2 124
#define W_2 108
#define BATCH 4
#define C_0 (BATCH*H_0*W_0)
#define C_1 (BATCH*H_1*W_1)
#define C_2 (BATCH*H_2*W_2)

// packed f32x2 FMA: d = a*b + d elementwise on 32-bit halves
#define FMA2(d, a, b) \
    asm("fma.rn.f32x2 %0, %1, %2, %3;" : "=l"(d) : "l"(a), "l"(b), "l"(d))
#define UNPACK2(lo, hi, p) \
    asm("mov.b64 {%0, %1}, %2;" : "=r"(lo), "=r"(hi) : "l"(p))

// ---- static device scratch (allocation-free rule) ----
static __device__ __align__(16) float g_vf0[N_0*64];
static __device__ __align__(16) float g_vf1[N_1*64];
static __device__ __align__(16) float g_vf2[N_2*64];
static __device__ int g_own0[C_0];
static __device__ int g_own1[C_1];
static __device__ int g_own2[C_2];
static __device__ __align__(16) float g_sf0[(size_t)C_0*64];
static __device__ __align__(16) float g_sf1[(size_t)C_1*64];
static __device__ __align__(16) float g_sf2[(size_t)C_2*64];
static __device__ __align__(16) float g_up1[(size_t)C_1*64];
static __device__ __align__(16) float g_fused1[(size_t)C_1*64];
static __device__ __align__(16) float g_up0[(size_t)C_0*64];
static __device__ __align__(16) float g_wT[2*128*9*64];
static __device__ float g_fbias[2*64];

// ---- fused clear: all sf buffers to 0.f, all own buffers to -1 ----
__global__ void clear_all_kernel(float* sf0, float* sf1, float* sf2,
                                 int* own0, int* own1, int* own2) {
    size_t i = (size_t)blockIdx.x * blockDim.x + threadIdx.x;
    size_t st = (size_t)gridDim.x * blockDim.x;
    for (size_t k = i; k < (size_t)C_0*64; k += st) sf0[k] = 0.f;
    for (size_t k = i; k < (size_t)C_1*64; k += st) sf1[k] = 0.f;
    for (size_t k = i; k < (size_t)C_2*64; k += st) sf2[k] = 0.f;
    for (size_t k = i; k < C_0; k += st) own0[k] = -1;
    for (size_t k = i; k < C_1; k += st) own1[k] = -1;
    for (size_t k = i; k < C_2; k += st) own2[k] = -1;
}

// ---- weight prep: transpose conv weights [l][ci][tap][co] + fold BN ----
__global__ void prep_weights_kernel(const float* __restrict__ fw, const float* __restrict__ fg,
                                    const float* __restrict__ fb, const float* __restrict__ fm,
                                    const float* __restrict__ fv, float* __restrict__ wT,
                                    float* __restrict__ fbias) {
    int idx = blockIdx.x * blockDim.x + threadIdx.x;
    if (idx >= 2*128*9*64) return;
    int co  = idx & 63;
    int tap = (idx >> 6) % 9;
    int ci  = (idx / 576) & 127;
    int l   = idx / (576*128);
    float s = fg[l*64+co] * rsqrtf(fv[l*64+co] + EPSV);
    wT[idx] = fw[((size_t)(l*64+co)*128 + ci)*9 + tap] * s;
    if (idx < 128) {
        float s2 = fg[idx] * rsqrtf(fv[idx] + EPSV);
        fbias[idx] = fb[idx] - fm[idx]*s2;
    }
}

// ---- VFE: one voxel per 64-thread block ----
__global__ __launch_bounds__(64) void vfe_kernel(
    const float4* __restrict__ voxels, const int* __restrict__ num_pts,
    const float* __restrict__ w1, const float* __restrict__ g1, const float* __restrict__ b1,
    const float* __restrict__ rm1, const float* __restrict__ rv1,
    const float* __restrict__ w2, const float* __restrict__ g2, const float* __restrict__ b2,
    const float* __restrict__ rm2, const float* __restrict__ rv2,
    float* __restrict__ vf)
{
    __shared__ float4 vox[32];
    __shared__ float msh[3];
    __shared__ __align__(16) float xs[32][64];
    __shared__ float gm[64];

    int i = blockIdx.x;
    int c = threadIdx.x;
    if (c < 32) vox[c] = voxels[(size_t)i*32 + c];
    int np = num_pts[i];
    __syncthreads();
    if (c < 3) {
        const float* vv = (const float*)vox;
        float s = 0.f;
        #pragma unroll
        for (int t = 0; t < 32; t++) s += vv[t*4 + c];
        msh[c] = s / (float)np;
    }
    __syncthreads();

    float w1c[9];
    #pragma unroll
    for (int j = 0; j < 9; j++) w1c[j] = w1[j*64 + c];
    float a0 = w1c[0] + w1c[4] + w1c[7];
    float a1 = w1c[1] + w1c[5] + w1c[8];
    float a2 = w1c[2] + w1c[6];
    float a3 = w1c[3];
    float cst = -(msh[0]*(w1c[4]+w1c[7]) + msh[1]*(w1c[5]+w1c[8]) + msh[2]*w1c[6]);
    float s1 = g1[c] * rsqrtf(rv1[c] + EPSV);
    float bb1 = b1[c] - rm1[c]*s1;

    float gmax = -1e30f;
    #pragma unroll
    for (int t = 0; t < 32; t++) {
        float4 v = vox[t];
        float d = cst + v.x*a0 + v.y*a1 + v.z*a2 + v.w*a3;
        float h = fmaxf(d*s1 + bb1, 0.f);
        xs[t][c] = h;
        gmax = fmaxf(gmax, h);
    }
    gm[c] = gmax;
    __syncthreads();

    float wr[64];
    #pragma unroll
    for (int k = 0; k < 64; k++) wr[k] = w2[k*64 + c];
    float gdot = 0.f;
    #pragma unroll
    for (int j = 0; j < 64; j++) gdot = fmaf(gm[j], w2[(64+j)*64 + c], gdot);
    float s2 = g2[c] * rsqrtf(rv2[c] + EPSV);
    float bb2 = b2[c] - rm2[c]*s2;

    float vmax = 0.f;
    for (int t = 0; t < np; t++) {
        const float4* row = (const float4*)xs[t];
        float ac0 = gdot, ac1 = 0.f, ac2 = 0.f, ac3 = 0.f;
        #pragma unroll
        for (int q = 0; q < 16; q += 4) {
            float4 x0 = row[q+0], x1 = row[q+1], x2 = row[q+2], x3 = row[q+3];
            ac0 = fmaf(x0.x, wr[4*q+0],  fmaf(x0.y, wr[4*q+1],  fmaf(x0.z, wr[4*q+2],  fmaf(x0.w, wr[4*q+3],  ac0))));
            ac1 = fmaf(x1.x, wr[4*q+4],  fmaf(x1.y, wr[4*q+5],  fmaf(x1.z, wr[4*q+6],  fmaf(x1.w, wr[4*q+7],  ac1))));
            ac2 = fmaf(x2.x, wr[4*q+8],  fmaf(x2.y, wr[4*q+9],  fmaf(x2.z, wr[4*q+10], fmaf(x2.w, wr[4*q+11], ac2))));
            ac3 = fmaf(x3.x, wr[4*q+12], fmaf(x3.y, wr[4*q+13], fmaf(x3.z, wr[4*q+14], fmaf(x3.w, wr[4*q+15], ac3))));
        }
        float dot = (ac0 + ac1) + (ac2 + ac3);
        vmax = fmaxf(vmax, fmaxf(dot*s2 + bb2, 0.f));
    }
    vf[(size_t)i*64 + c] = vmax;
}

// ---- scatter: last-index-wins ----
__global__ void owner_kernel(const int* __restrict__ coords, int* __restrict__ own,
                             int N, int H, int W) {
    int i = blockIdx.x * blockDim.x + threadIdx.x;
    if (i >= N) return;
    int b = coords[i*4 + 0];
    int y = min(max(coords[i*4 + 2], 0), H-1);
    int x = min(max(coords[i*4 + 3], 0), W-1);
    atomicMax(&own[(b*H + y)*W + x], i);
}
__global__ __launch_bounds__(64) void scatter_kernel(
    const int* __restrict__ coords, const int* __restrict__ own,
    const float* __restrict__ vf, float* __restrict__ sf, int H, int W)
{
    int i = blockIdx.x;
    int c = threadIdx.x;
    int b = coords[i*4 + 0];
    int y = min(max(coords[i*4 + 2], 0), H-1);
    int x = min(max(coords[i*4 + 3], 0), W-1);
    if (own[(b*H + y)*W + x] != i) return;
    sf[((size_t)(b*64 + c)*H + y)*W + x] = vf[(size_t)i*64 + c];
}

// ---- bilinear 2x upsample (jax half-pixel-center) ----
__global__ void upsample_kernel(const float* __restrict__ in, float* __restrict__ out,
                                int Hi, int Wi) {
    int Ho = Hi*2, Wo = Wi*2;
    long long idx = (long long)blockIdx.x * blockDim.x + threadIdx.x;
    long long total = (long long)BATCH*64*Ho*Wo;
    if (idx >= total) return;
    int x  = (int)(idx % Wo);
    int y  = (int)((idx / Wo) % Ho);
    int ch = (int)(idx / ((long long)Wo*Ho));
    float fy = 0.5f*y - 0.25f;
    float fx = 0.5f*x - 0.25f;
    int y0 = (int)floorf(fy); float wy = fy - (float)y0;
    int x0 = (int)floorf(fx); float wx = fx - (float)x0;
    int ya = max(y0, 0), yb = min(y0+1, Hi-1);
    int xa = max(x0, 0), xb = min(x0+1, Wi-1);
    const float* p = in + (size_t)ch*Hi*Wi;
    float v00 = p[ya*Wi+xa], v01 = p[ya*Wi+xb];
    float v10 = p[yb*Wi+xa], v11 = p[yb*Wi+xb];
    out[idx] = (1.f-wy)*((1.f-wx)*v00 + wx*v01) + wy*((1.f-wx)*v10 + wx*v11);
}

// ---- fused 3x3 conv + BN + relu, FFMA2 + per-kx register cache ----
// 128 threads: tile 16(x) x 8(y) px x 64 out-ch; thread = 8px x 4 packed co-pairs.
__global__ __launch_bounds__(128) void conv_kernel(
    const float* __restrict__ srcA, const float* __restrict__ srcB,
    const float* __restrict__ wT, const float* __restrict__ fbias,
    float* __restrict__ out, int H, int W)
{
    __shared__ __align__(16) float ws[4*9*64];
    __shared__ __align__(16) float2 ins2[4][10][18];   // pre-duplicated broadcast pairs
    int tx = threadIdx.x;
    int pg = tx & 15;
    int cg = tx >> 4;
    int x0 = blockIdx.x * 16;
    int y0 = blockIdx.y * 8;
    int b  = blockIdx.z;

    unsigned long long acc[8][4];
    #pragma unroll
    for (int y = 0; y < 8; y++)
        #pragma unroll
        for (int j = 0; j < 4; j++) acc[y][j] = 0ULL;

    for (int ci0 = 0; ci0 < 128; ci0 += 4) {
        {
            const float4* wsrc = (const float4*)(wT + (size_t)ci0*576);
            float4* wdst = (float4*)ws;
            for (int e = tx; e < 576; e += 128) wdst[e] = wsrc[e];
        }
        for (int e = tx; e < 720; e += 128) {
            int cc = e / 180; int r = e - cc*180;
            int yy = r / 18;  int xx = r - yy*18;
            int gy = y0 + yy - 1, gx = x0 + xx - 1;
            int ci = ci0 + cc;
            const float* src = (ci < 64) ? srcA : srcB;
            float v = 0.f;
            if (gy >= 0 && gy < H && gx >= 0 && gx < W)
                v = src[((size_t)(b*64 + (ci & 63))*H + gy)*W + gx];
            ins2[cc][yy][xx] = make_float2(v, v);
        }
        __syncthreads();

        #pragma unroll 1
        for (int cc = 0; cc < 4; cc++) {
            #pragma unroll
            for (int kx = 0; kx < 3; kx++) {
                // cache the 10-row column once, reuse for 3 ky taps
                unsigned long long ivc[10];
                #pragma unroll
                for (int r = 0; r < 10; r++)
                    ivc[r] = *reinterpret_cast<const unsigned long long*>(&ins2[cc][r][pg+kx]);
                #pragma unroll
                for (int ky = 0; ky < 3; ky++) {
                    int t = ky*3 + kx;
                    const ulonglong2* wp = reinterpret_cast<const ulonglong2*>(&ws[(cc*9+t)*64 + cg*8]);
                    ulonglong2 wA = wp[0];
                    ulonglong2 wB = wp[1];
                    #pragma unroll
                    for (int y = 0; y < 8; y++) {
                        unsigned long long iv = ivc[y+ky];
                        FMA2(acc[y][0], iv, wA.x);
                        FMA2(acc[y][1], iv, wA.y);
                        FMA2(acc[y][2], iv, wB.x);
                        FMA2(acc[y][3], iv, wB.y);
                    }
                }
            }
        }
        __syncthreads();
    }
    int x = x0 + pg;
    if (x < W) {
        #pragma unroll
        for (int j = 0; j < 4; j++) {
            float b0 = fbias[cg*8 + 2*j];
            float b1 = fbias[cg*8 + 2*j + 1];
            #pragma unroll
            for (int y = 0; y < 8; y++) {
                unsigned lo, hi;
                UNPACK2(lo, hi, acc[y][j]);
                float v0 = __uint_as_float(lo) + b0;
                float v1 = __uint_as_float(hi) + b1;
                out[((size_t)(b*64 + cg*8 + 2*j)*H + (y0+y))*W + x]   = fmaxf(v0, 0.f);
                out[((size_t)(b*64 + cg*8 + 2*j+1)*H + (y0+y))*W + x] = fmaxf(v1, 0.f);
            }
        }
    }
}

extern "C" void kernel_launch(void* const* d_in, const int* in_sizes, int n_in,
                              void* d_out, int out_size) {
    // ---- input index mapping: dict order vs signature order ----
    int IV[3], INP[3], IC[3];
    int iw1,ig1,ib1,irm1,irv1,iw2,ig2,ib2,irm2,irv2,ifw,ifg,ifb,ifm,ifv;
    if (in_sizes[1] == N_0) { // dict order
        IV[0]=0; INP[0]=1; IC[0]=2; IV[1]=3; INP[1]=4; IC[1]=5; IV[2]=6; INP[2]=7; IC[2]=8;
        iw1=9; ig1=10; ib1=11; irm1=12; irv1=13; iw2=14; ig2=15; ib2=16; irm2=17; irv2=18;
        ifw=19; ifg=20; ifb=21; ifm=22; ifv=23;
    } else { // signature order
        IV[0]=0; IV[1]=1; IV[2]=2;
        iw1=3; ig1=4; ib1=5; irm1=6; irv1=7; iw2=8; ig2=9; ib2=10; irm2=11; irv2=12;
        ifw=13; ifg=14; ifb=15; ifm=16; ifv=17;
        INP[0]=18; INP[1]=19; INP[2]=20; IC[0]=21; IC[1]=22; IC[2]=23;
    }
    const float* w1 = (const float*)d_in[iw1];
    const float* g1 = (const float*)d_in[ig1];
    const float* b1 = (const float*)d_in[ib1];
    const float* rm1 = (const float*)d_in[irm1];
    const float* rv1 = (const float*)d_in[irv1];
    const float* w2 = (const float*)d_in[iw2];
    const float* g2 = (const float*)d_in[ig2];
    const float* b2 = (const float*)d_in[ib2];
    const float* rm2 = (const float*)d_in[irm2];
    const float* rv2 = (const float*)d_in[irv2];

    float *vf[3], *sf[3], *up1, *fused1, *up0, *wT, *fbias;
    int *own[3];
    cudaGetSymbolAddress((void**)&vf[0], g_vf0);
    cudaGetSymbolAddress((void**)&vf[1], g_vf1);
    cudaGetSymbolAddress((void**)&vf[2], g_vf2);
    cudaGetSymbolAddress((void**)&own[0], g_own0);
    cudaGetSymbolAddress((void**)&own[1], g_own1);
    cudaGetSymbolAddress((void**)&own[2], g_own2);
    cudaGetSymbolAddress((void**)&sf[0], g_sf0);
    cudaGetSymbolAddress((void**)&sf[1], g_sf1);
    cudaGetSymbolAddress((void**)&sf[2], g_sf2);
    cudaGetSymbolAddress((void**)&up1, g_up1);
    cudaGetSymbolAddress((void**)&fused1, g_fused1);
    cudaGetSymbolAddress((void**)&up0, g_up0);
    cudaGetSymbolAddress((void**)&wT, g_wT);
    cudaGetSymbolAddress((void**)&fbias, g_fbias);

    const int NS[3] = {N_0, N_1, N_2};
    const int HS[3] = {H_0, H_1, H_2};
    const int WS[3] = {W_0, W_1, W_2};

    // launch order chosen so ncu (-s 5 -c 1) profiles launch #6 = vfe_kernel(scale 0)
    clear_all_kernel<<<2048, 256>>>(sf[0], sf[1], sf[2], own[0], own[1], own[2]);   // 1
    prep_weights_kernel<<<(2*128*9*64 + 255)/256, 256>>>(                            // 2
        (const float*)d_in[ifw], (const float*)d_in[ifg], (const float*)d_in[ifb],
        (const float*)d_in[ifm], (const float*)d_in[ifv], wT, fbias);
    for (int s = 0; s < 3; s++)                                                      // 3,4,5
        owner_kernel<<<(NS[s]+255)/256, 256>>>((const int*)d_in[IC[s]], own[s], NS[s], HS[s], WS[s]);
    for (int s = 0; s < 3; s++) {                                                    // 6,7,8
        vfe_kernel<<<NS[s], 64>>>(
            (const float4*)d_in[IV[s]], (const int*)d_in[INP[s]],
            w1 + s*576, g1 + s*64, b1 + s*64, rm1 + s*64, rv1 + s*64,
            w2 + s*8192, g2 + s*64, b2 + s*64, rm2 + s*64, rv2 + s*64,
            vf[s]);
    }
    for (int s = 0; s < 3; s++)                                                      // 9,10,11
        scatter_kernel<<<NS[s], 64>>>((const int*)d_in[IC[s]], own[s], vf[s], sf[s], HS[s], WS[s]);

    {
        long long tot = (long long)BATCH*64*H_1*W_1;
        upsample_kernel<<<(unsigned)((tot+255)/256), 256>>>(sf[2], up1, H_2, W_2);
        dim3 grid((W_1+15)/16, H_1/8, BATCH);
        conv_kernel<<<grid, 128>>>(sf[1], up1, wT + 128*576, fbias + 64, fused1, H_1, W_1);
    }
    {
        long long tot = (long long)BATCH*64*H_0*W_0;
        upsample_kernel<<<(unsigned)((tot+255)/256), 256>>>(fused1, up0, H_1, W_1);
        dim3 grid((W_0+15)/16, H_0/8, BATCH);
        conv_kernel<<<grid, 128>>>(sf[0], up0, wT, fbias, (float*)d_out, H_0, W_0);
    }
    (void)n_in; (void)out_size;
}

// round 12
// speedup vs baseline: 1.4716x; 1.4716x over previous
#include <cuda_runtime.h>

#define EPSV 1e-3f
#define N_0 40000
#define N_1 20000
#define N_2 8000
#define H_0 496
#define W_0 432
#define H_1 248
#define W_1 216
#define H_2 124
#define W_2 108
#define BATCH 4
#define C_0 (BATCH*H_0*W_0)
#define C_1 (BATCH*H_1*W_1)
#define C_2 (BATCH*H_2*W_2)

// packed f32x2 FMA
#define FMA2(d, a, b) \
    asm("fma.rn.f32x2 %0, %1, %2, %3;" : "=l"(d) : "l"(a), "l"(b), "l"(d))
#define UNPACK2(lo, hi, p) \
    asm("mov.b64 {%0, %1}, %2;" : "=r"(lo), "=r"(hi) : "l"(p))

// ---- static device scratch ----
static __device__ __align__(16) float g_vf0[N_0*64];
static __device__ __align__(16) float g_vf1[N_1*64];
static __device__ __align__(16) float g_vf2[N_2*64];
static __device__ int g_own0[C_0];
static __device__ int g_own1[C_1];
static __device__ int g_own2[C_2];
static __device__ __align__(16) float g_sf2[(size_t)C_2*64];
static __device__ __align__(16) float g_up1[(size_t)C_1*64];
static __device__ __align__(16) float g_acc1[(size_t)C_1*64];
static __device__ __align__(16) float g_fused1[(size_t)C_1*64];
static __device__ __align__(16) float g_up0[(size_t)C_0*64];
static __device__ __align__(16) float g_acc0[(size_t)C_0*64];
static __device__ __align__(16) float g_wT[2*128*9*64];
static __device__ float g_fbias[2*64];

// ---- clears: sf2 to 0, owners to -1 ----
__global__ void clear_all_kernel(float* sf2, int* own0, int* own1, int* own2) {
    size_t i = (size_t)blockIdx.x * blockDim.x + threadIdx.x;
    size_t st = (size_t)gridDim.x * blockDim.x;
    for (size_t k = i; k < (size_t)C_2*64; k += st) sf2[k] = 0.f;
    for (size_t k = i; k < C_0; k += st) own0[k] = -1;
    for (size_t k = i; k < C_1; k += st) own1[k] = -1;
    for (size_t k = i; k < C_2; k += st) own2[k] = -1;
}

// ---- weight prep: [l][ci][tap][co] + fold BN ----
__global__ void prep_weights_kernel(const float* __restrict__ fw, const float* __restrict__ fg,
                                    const float* __restrict__ fb, const float* __restrict__ fm,
                                    const float* __restrict__ fv, float* __restrict__ wT,
                                    float* __restrict__ fbias) {
    int idx = blockIdx.x * blockDim.x + threadIdx.x;
    if (idx >= 2*128*9*64) return;
    int co  = idx & 63;
    int tap = (idx >> 6) % 9;
    int ci  = (idx / 576) & 127;
    int l   = idx / (576*128);
    float s = fg[l*64+co] * rsqrtf(fv[l*64+co] + EPSV);
    wT[idx] = fw[((size_t)(l*64+co)*128 + ci)*9 + tap] * s;
    if (idx < 128) {
        float s2 = fg[idx] * rsqrtf(fv[idx] + EPSV);
        fbias[idx] = fb[idx] - fm[idx]*s2;
    }
}

// ---- VFE: one voxel per 64-thread block ----
__global__ __launch_bounds__(64) void vfe_kernel(
    const float4* __restrict__ voxels, const int* __restrict__ num_pts,
    const float* __restrict__ w1, const float* __restrict__ g1, const float* __restrict__ b1,
    const float* __restrict__ rm1, const float* __restrict__ rv1,
    const float* __restrict__ w2, const float* __restrict__ g2, const float* __restrict__ b2,
    const float* __restrict__ rm2, const float* __restrict__ rv2,
    float* __restrict__ vf)
{
    __shared__ float4 vox[32];
    __shared__ float msh[3];
    __shared__ __align__(16) float xs[32][64];
    __shared__ float gm[64];

    int i = blockIdx.x;
    int c = threadIdx.x;
    if (c < 32) vox[c] = voxels[(size_t)i*32 + c];
    int np = num_pts[i];
    __syncthreads();
    if (c < 3) {
        const float* vv = (const float*)vox;
        float s = 0.f;
        #pragma unroll
        for (int t = 0; t < 32; t++) s += vv[t*4 + c];
        msh[c] = s / (float)np;
    }
    __syncthreads();

    float w1c[9];
    #pragma unroll
    for (int j = 0; j < 9; j++) w1c[j] = w1[j*64 + c];
    float a0 = w1c[0] + w1c[4] + w1c[7];
    float a1 = w1c[1] + w1c[5] + w1c[8];
    float a2 = w1c[2] + w1c[6];
    float a3 = w1c[3];
    float cst = -(msh[0]*(w1c[4]+w1c[7]) + msh[1]*(w1c[5]+w1c[8]) + msh[2]*w1c[6]);
    float s1 = g1[c] * rsqrtf(rv1[c] + EPSV);
    float bb1 = b1[c] - rm1[c]*s1;

    float gmax = -1e30f;
    #pragma unroll
    for (int t = 0; t < 32; t++) {
        float4 v = vox[t];
        float d = cst + v.x*a0 + v.y*a1 + v.z*a2 + v.w*a3;
        float h = fmaxf(d*s1 + bb1, 0.f);
        xs[t][c] = h;
        gmax = fmaxf(gmax, h);
    }
    gm[c] = gmax;
    __syncthreads();

    float wr[64];
    #pragma unroll
    for (int k = 0; k < 64; k++) wr[k] = w2[k*64 + c];
    float gdot = 0.f;
    #pragma unroll
    for (int j = 0; j < 64; j++) gdot = fmaf(gm[j], w2[(64+j)*64 + c], gdot);
    float s2 = g2[c] * rsqrtf(rv2[c] + EPSV);
    float bb2 = b2[c] - rm2[c]*s2;

    float vmax = 0.f;
    for (int t = 0; t < np; t++) {
        const float4* row = (const float4*)xs[t];
        float ac0 = gdot, ac1 = 0.f, ac2 = 0.f, ac3 = 0.f;
        #pragma unroll
        for (int q = 0; q < 16; q += 4) {
            float4 x0 = row[q+0], x1 = row[q+1], x2 = row[q+2], x3 = row[q+3];
            ac0 = fmaf(x0.x, wr[4*q+0],  fmaf(x0.y, wr[4*q+1],  fmaf(x0.z, wr[4*q+2],  fmaf(x0.w, wr[4*q+3],  ac0))));
            ac1 = fmaf(x1.x, wr[4*q+4],  fmaf(x1.y, wr[4*q+5],  fmaf(x1.z, wr[4*q+6],  fmaf(x1.w, wr[4*q+7],  ac1))));
            ac2 = fmaf(x2.x, wr[4*q+8],  fmaf(x2.y, wr[4*q+9],  fmaf(x2.z, wr[4*q+10], fmaf(x2.w, wr[4*q+11], ac2))));
            ac3 = fmaf(x3.x, wr[4*q+12], fmaf(x3.y, wr[4*q+13], fmaf(x3.z, wr[4*q+14], fmaf(x3.w, wr[4*q+15], ac3))));
        }
        float dot = (ac0 + ac1) + (ac2 + ac3);
        vmax = fmaxf(vmax, fmaxf(dot*s2 + bb2, 0.f));
    }
    vf[(size_t)i*64 + c] = vmax;
}

// ---- owner: last-index-wins ----
__global__ void owner_kernel(const int* __restrict__ coords, int* __restrict__ own,
                             int N, int H, int W) {
    int i = blockIdx.x * blockDim.x + threadIdx.x;
    if (i >= N) return;
    int b = coords[i*4 + 0];
    int y = min(max(coords[i*4 + 2], 0), H-1);
    int x = min(max(coords[i*4 + 3], 0), W-1);
    atomicMax(&own[(b*H + y)*W + x], i);
}
// dense BEV scatter (only for scale 2)
__global__ __launch_bounds__(64) void scatter_kernel(
    const int* __restrict__ coords, const int* __restrict__ own,
    const float* __restrict__ vf, float* __restrict__ sf, int H, int W)
{
    int i = blockIdx.x;
    int c = threadIdx.x;
    int b = coords[i*4 + 0];
    int y = min(max(coords[i*4 + 2], 0), H-1);
    int x = min(max(coords[i*4 + 3], 0), W-1);
    if (own[(b*H + y)*W + x] != i) return;
    sf[((size_t)(b*64 + c)*H + y)*W + x] = vf[(size_t)i*64 + c];
}

// ---- bilinear 2x upsample (jax half-pixel-center) ----
__global__ void upsample_kernel(const float* __restrict__ in, float* __restrict__ out,
                                int Hi, int Wi) {
    int Ho = Hi*2, Wo = Wi*2;
    long long idx = (long long)blockIdx.x * blockDim.x + threadIdx.x;
    long long total = (long long)BATCH*64*Ho*Wo;
    if (idx >= total) return;
    int x  = (int)(idx % Wo);
    int y  = (int)((idx / Wo) % Ho);
    int ch = (int)(idx / ((long long)Wo*Ho));
    float fy = 0.5f*y - 0.25f;
    float fx = 0.5f*x - 0.25f;
    int y0 = (int)floorf(fy); float wy = fy - (float)y0;
    int x0 = (int)floorf(fx); float wx = fx - (float)x0;
    int ya = max(y0, 0), yb = min(y0+1, Hi-1);
    int xa = max(x0, 0), xb = min(x0+1, Wi-1);
    const float* p = in + (size_t)ch*Hi*Wi;
    float v00 = p[ya*Wi+xa], v01 = p[ya*Wi+xb];
    float v10 = p[yb*Wi+xa], v11 = p[yb*Wi+xb];
    out[idx] = (1.f-wy)*((1.f-wx)*v00 + wx*v01) + wy*((1.f-wx)*v10 + wx*v11);
}

// ---- dense 3x3 conv over Cin=64 (up half only), raw accumulators (no bias/relu) ----
__global__ __launch_bounds__(128) void conv_dense_kernel(
    const float* __restrict__ src,
    const float* __restrict__ wTd,   // [ci 0..63][tap][co] (dense half, pre-offset)
    float* __restrict__ acc_out, int H, int W)
{
    __shared__ __align__(16) float ws[4*9*64];
    __shared__ __align__(16) float2 ins2[4][10][18];
    int tx = threadIdx.x;
    int pg = tx & 15;
    int cg = tx >> 4;
    int x0 = blockIdx.x * 16;
    int y0 = blockIdx.y * 8;
    int b  = blockIdx.z;

    unsigned long long acc[8][4];
    #pragma unroll
    for (int y = 0; y < 8; y++)
        #pragma unroll
        for (int j = 0; j < 4; j++) acc[y][j] = 0ULL;

    for (int ci0 = 0; ci0 < 64; ci0 += 4) {
        {
            const float4* wsrc = (const float4*)(wTd + (size_t)ci0*576);
            float4* wdst = (float4*)ws;
            for (int e = tx; e < 576; e += 128) wdst[e] = wsrc[e];
        }
        for (int e = tx; e < 720; e += 128) {
            int cc = e / 180; int r = e - cc*180;
            int yy = r / 18;  int xx = r - yy*18;
            int gy = y0 + yy - 1, gx = x0 + xx - 1;
            float v = 0.f;
            if (gy >= 0 && gy < H && gx >= 0 && gx < W)
                v = src[((size_t)(b*64 + ci0 + cc)*H + gy)*W + gx];
            ins2[cc][yy][xx] = make_float2(v, v);
        }
        __syncthreads();

        #pragma unroll 1
        for (int cc = 0; cc < 4; cc++) {
            #pragma unroll
            for (int t = 0; t < 9; t++) {
                int ky = t/3, kx = t - ky*3;
                const ulonglong2* wp = reinterpret_cast<const ulonglong2*>(&ws[(cc*9+t)*64 + cg*8]);
                ulonglong2 wA = wp[0];
                ulonglong2 wB = wp[1];
                const unsigned long long* ivp =
                    reinterpret_cast<const unsigned long long*>(&ins2[cc][ky][pg+kx]);
                #pragma unroll
                for (int y = 0; y < 8; y++) {
                    unsigned long long iv = ivp[y*18];
                    FMA2(acc[y][0], iv, wA.x);
                    FMA2(acc[y][1], iv, wA.y);
                    FMA2(acc[y][2], iv, wB.x);
                    FMA2(acc[y][3], iv, wB.y);
                }
            }
        }
        __syncthreads();
    }
    int x = x0 + pg;
    if (x < W) {
        #pragma unroll
        for (int j = 0; j < 4; j++) {
            #pragma unroll
            for (int y = 0; y < 8; y++) {
                unsigned lo, hi;
                UNPACK2(lo, hi, acc[y][j]);
                acc_out[((size_t)(b*64 + cg*8 + 2*j)*H + (y0+y))*W + x]   = __uint_as_float(lo);
                acc_out[((size_t)(b*64 + cg*8 + 2*j+1)*H + (y0+y))*W + x] = __uint_as_float(hi);
            }
        }
    }
}

// ---- sparse scatter-conv: sf half via per-point 9-tap stencil, atomicAdd into acc ----
// block = 64 threads (co), P=4 points per block.
__global__ __launch_bounds__(64) void scatter_conv_kernel(
    const int* __restrict__ coords, const int* __restrict__ own,
    const float* __restrict__ vf,
    const float* __restrict__ wS,   // [ci 0..63][tap][co] (sparse half)
    float* __restrict__ acc_out, int N, int H, int W)
{
    __shared__ __align__(16) float vfs[4][64];
    __shared__ int pb[4], py[4], px[4], pv[4];
    int co = threadIdx.x;
    int base = blockIdx.x * 4;

    if (co < 4) {
        int ip = base + co;
        int v = 0, b = 0, y = 0, x = 0;
        if (ip < N) {
            b = coords[ip*4 + 0];
            y = min(max(coords[ip*4 + 2], 0), H-1);
            x = min(max(coords[ip*4 + 3], 0), W-1);
            v = (own[(b*H + y)*W + x] == ip) ? 1 : 0;
        }
        pb[co] = b; py[co] = y; px[co] = x; pv[co] = v;
    }
    __syncthreads();
    #pragma unroll
    for (int p = 0; p < 4; p++) {
        int ip = base + p;
        vfs[p][co] = (ip < N && pv[p]) ? vf[(size_t)ip*64 + co] : 0.f;
    }
    __syncthreads();

    float a[4][9];
    #pragma unroll
    for (int p = 0; p < 4; p++)
        #pragma unroll
        for (int t = 0; t < 9; t++) a[p][t] = 0.f;

    for (int ci = 0; ci < 64; ci++) {
        float wv[9];
        #pragma unroll
        for (int t = 0; t < 9; t++) wv[t] = wS[(size_t)ci*576 + t*64 + co];
        #pragma unroll
        for (int p = 0; p < 4; p++) {
            float v = vfs[p][ci];
            #pragma unroll
            for (int t = 0; t < 9; t++) a[p][t] = fmaf(v, wv[t], a[p][t]);
        }
    }

    #pragma unroll
    for (int p = 0; p < 4; p++) {
        if (!pv[p]) continue;
        int b = pb[p], y = py[p], x = px[p];
        #pragma unroll
        for (int t = 0; t < 9; t++) {
            int ky = t/3, kx = t - ky*3;
            int oy = y - ky + 1, ox = x - kx + 1;
            if (oy >= 0 && oy < H && ox >= 0 && ox < W)
                atomicAdd(&acc_out[((size_t)(b*64 + co)*H + oy)*W + ox], a[p][t]);
        }
    }
}

// ---- finalize: out = relu(acc + bias) ----
__global__ void finalize_kernel(const float* __restrict__ acc, const float* __restrict__ fbias,
                                float* __restrict__ out, int H, int W) {
    long long idx = (long long)blockIdx.x * blockDim.x + threadIdx.x;
    long long total = (long long)BATCH*64*H*W;
    if (idx >= total) return;
    int co = (int)((idx / ((long long)H*W)) & 63);
    out[idx] = fmaxf(acc[idx] + fbias[co], 0.f);
}

extern "C" void kernel_launch(void* const* d_in, const int* in_sizes, int n_in,
                              void* d_out, int out_size) {
    int IV[3], INP[3], IC[3];
    int iw1,ig1,ib1,irm1,irv1,iw2,ig2,ib2,irm2,irv2,ifw,ifg,ifb,ifm,ifv;
    if (in_sizes[1] == N_0) { // dict order
        IV[0]=0; INP[0]=1; IC[0]=2; IV[1]=3; INP[1]=4; IC[1]=5; IV[2]=6; INP[2]=7; IC[2]=8;
        iw1=9; ig1=10; ib1=11; irm1=12; irv1=13; iw2=14; ig2=15; ib2=16; irm2=17; irv2=18;
        ifw=19; ifg=20; ifb=21; ifm=22; ifv=23;
    } else { // signature order
        IV[0]=0; IV[1]=1; IV[2]=2;
        iw1=3; ig1=4; ib1=5; irm1=6; irv1=7; iw2=8; ig2=9; ib2=10; irm2=11; irv2=12;
        ifw=13; ifg=14; ifb=15; ifm=16; ifv=17;
        INP[0]=18; INP[1]=19; INP[2]=20; IC[0]=21; IC[1]=22; IC[2]=23;
    }
    const float* w1 = (const float*)d_in[iw1];
    const float* g1 = (const float*)d_in[ig1];
    const float* b1 = (const float*)d_in[ib1];
    const float* rm1 = (const float*)d_in[irm1];
    const float* rv1 = (const float*)d_in[irv1];
    const float* w2 = (const float*)d_in[iw2];
    const float* g2 = (const float*)d_in[ig2];
    const float* b2 = (const float*)d_in[ib2];
    const float* rm2 = (const float*)d_in[irm2];
    const float* rv2 = (const float*)d_in[irv2];

    float *vf[3], *sf2, *up1, *acc1, *fused1, *up0, *acc0, *wT, *fbias;
    int *own[3];
    cudaGetSymbolAddress((void**)&vf[0], g_vf0);
    cudaGetSymbolAddress((void**)&vf[1], g_vf1);
    cudaGetSymbolAddress((void**)&vf[2], g_vf2);
    cudaGetSymbolAddress((void**)&own[0], g_own0);
    cudaGetSymbolAddress((void**)&own[1], g_own1);
    cudaGetSymbolAddress((void**)&own[2], g_own2);
    cudaGetSymbolAddress((void**)&sf2, g_sf2);
    cudaGetSymbolAddress((void**)&up1, g_up1);
    cudaGetSymbolAddress((void**)&acc1, g_acc1);
    cudaGetSymbolAddress((void**)&fused1, g_fused1);
    cudaGetSymbolAddress((void**)&up0, g_up0);
    cudaGetSymbolAddress((void**)&acc0, g_acc0);
    cudaGetSymbolAddress((void**)&wT, g_wT);
    cudaGetSymbolAddress((void**)&fbias, g_fbias);

    const int NS[3] = {N_0, N_1, N_2};
    const int HS[3] = {H_0, H_1, H_2};
    const int WS[3] = {W_0, W_1, W_2};

    clear_all_kernel<<<1024, 256>>>(sf2, own[0], own[1], own[2]);
    prep_weights_kernel<<<(2*128*9*64 + 255)/256, 256>>>(
        (const float*)d_in[ifw], (const float*)d_in[ifg], (const float*)d_in[ifb],
        (const float*)d_in[ifm], (const float*)d_in[ifv], wT, fbias);
    for (int s = 0; s < 3; s++)
        owner_kernel<<<(NS[s]+255)/256, 256>>>((const int*)d_in[IC[s]], own[s], NS[s], HS[s], WS[s]);
    for (int s = 0; s < 3; s++)
        vfe_kernel<<<NS[s], 64>>>(
            (const float4*)d_in[IV[s]], (const int*)d_in[INP[s]],
            w1 + s*576, g1 + s*64, b1 + s*64, rm1 + s*64, rv1 + s*64,
            w2 + s*8192, g2 + s*64, b2 + s*64, rm2 + s*64, rv2 + s*64,
            vf[s]);
    // only scale 2 is materialized as a dense BEV grid
    scatter_kernel<<<NS[2], 64>>>((const int*)d_in[IC[2]], own[2], vf[2], sf2, HS[2], WS[2]);

    // ---- level 1 ----
    {
        long long tot = (long long)BATCH*64*H_1*W_1;
        upsample_kernel<<<(unsigned)((tot+255)/256), 256>>>(sf2, up1, H_2, W_2);
        dim3 grid((W_1+15)/16, H_1/8, BATCH);
        conv_dense_kernel<<<grid, 128>>>(up1, wT + 128*576 + 64*576, acc1, H_1, W_1);
        scatter_conv_kernel<<<(N_1+3)/4, 64>>>((const int*)d_in[IC[1]], own[1], vf[1],
                                               wT + 128*576, acc1, N_1, H_1, W_1);
        finalize_kernel<<<(unsigned)((tot+255)/256), 256>>>(acc1, fbias + 64, fused1, H_1, W_1);
    }
    // ---- level 0 ----
    {
        long long tot = (long long)BATCH*64*H_0*W_0;
        upsample_kernel<<<(unsigned)((tot+255)/256), 256>>>(fused1, up0, H_1, W_1);
        dim3 grid((W_0+15)/16, H_0/8, BATCH);
        conv_dense_kernel<<<grid, 128>>>(up0, wT + 64*576, acc0, H_0, W_0);
        scatter_conv_kernel<<<(N_0+3)/4, 64>>>((const int*)d_in[IC[0]], own[0], vf[0],
                                               wT, acc0, N_0, H_0, W_0);
        finalize_kernel<<<(unsigned)((tot+255)/256), 256>>>(acc0, fbias, (float*)d_out, H_0, W_0);
    }
    (void)n_in; (void)out_size;
}